// round 11
// baseline (speedup 1.0000x reference)
#include <cuda_runtime.h>
#include <cuda_bf16.h>
#include <math.h>

// result[b] = sigmoid( u^T X_b v + bias ),  u = basis^T w_h, v = basis^T w_v
// N = 512, BATCH = 256. x is (256, 512*512) fp32. Output (256,1) fp32.

#define NN 512
#define BATCH 256
#define HALVES 2                       // half-batches per batch in main kernel
#define HALF_F4 32768                  // float4s per half-batch (512 KB)
#define TOTAL_CTAS (BATCH * HALVES)    // 512 — single wave on 148+ SMs

__device__ __align__(16) float g_u[NN];
__device__ __align__(16) float g_v[NN];
__device__ float g_partial[BATCH * HALVES];
__device__ unsigned int g_done = 0;    // completion counter (reset by finalizer)

// ---------------------------------------------------------------------------
// Kernel 1: u[k] = sum_i w_h[i] * cu[i] * cos((2k+1) i pi / (2N)), same for v.
// Warp-per-k layout: 32 CTAs x 512 threads = 512 warps, warp w owns k = w.
// Each lane accumulates 16 terms (i = j*32 + lane -> coalesced wh/wv reads,
// deep cosf ILP), then ONE warp shfl reduction. No __syncthreads, no
// cross-warp stage, single wave -> short critical path.
// Integer phase mod 4N keeps the cosf argument in [0, 2pi) — full accuracy
// (sigmoid saturation amplifies absolute error in the big dot product, so
// fast-math __cosf is deliberately NOT used).
// ---------------------------------------------------------------------------
__global__ __launch_bounds__(512) void dct_prep(const float* __restrict__ wh,
                                                const float* __restrict__ wv) {
    const int t = threadIdx.x;
    const int lane = t & 31;
    const int k = blockIdx.x * 16 + (t >> 5);
    const int twokp1 = 2 * k + 1;

    float tu = 0.0f, tv = 0.0f;
    #pragma unroll
    for (int j = 0; j < 16; ++j) {
        const int i = j * 32 + lane;
        // cu[0] = sqrt(1/512), cu[i>0] = sqrt(2/512) = 1/16
        const float cu = (i == 0) ? 0.04419417382415922f : 0.0625f;
        const int m = (twokp1 * i) & 2047;                  // mod 4N
        const float c = cu * cosf((float)m * 0.0030679615757712823f);
        tu += wh[i] * c;
        tv += wv[i] * c;
    }

    #pragma unroll
    for (int o = 16; o; o >>= 1) {
        tu += __shfl_down_sync(0xffffffffu, tu, o);
        tv += __shfl_down_sync(0xffffffffu, tv, o);
    }
    if (lane == 0) { g_u[k] = tu; g_v[k] = tv; }
}

// ---------------------------------------------------------------------------
// Kernel 2 (persistent single-wave main + fused finalize):
// grid = (2, 256): CTA (q, b) streams half-batch q of batch b (512 KB,
// 128 float4-iterations per thread). All 512 CTAs co-resident -> one wave.
// x is read once with streaming (__ldcs, evict-first). v (512 floats) in
// shared as float4 (conflict-free LDS.128); u warp-uniform from shared.
// The LAST CTA (completion counter) reduces partials in fixed order,
// applies sigmoid, writes out, resets the counter for the next replay.
// ---------------------------------------------------------------------------
__global__ __launch_bounds__(256) void dct_main(const float* __restrict__ x,
                                                const float* __restrict__ bias,
                                                float* __restrict__ out) {
    __shared__ float4 sv4[NN / 4];   // all 512 v values
    __shared__ float su[256];        // u values for this half-batch
    __shared__ float sred[8];
    __shared__ bool s_last;

    const int t = threadIdx.x;
    const int q = blockIdx.x;        // half index (0 or 1)
    const int b = blockIdx.y;

    if (t < 128) sv4[t] = reinterpret_cast<const float4*>(g_v)[t];
    su[t] = g_u[q * 256 + t];
    __syncthreads();

    const float4* xp = reinterpret_cast<const float4*>(x)
                     + ((size_t)b << 16) + ((size_t)q << 15);

    float sum = 0.0f;
    #pragma unroll 16
    for (int i = t; i < HALF_F4; i += 256) {
        const float4 xv = __ldcs(xp + i);    // streaming: no reuse, evict-first
        const float4 vv = sv4[i & 127];      // l-group = i mod 128
        const float uk = su[i >> 7];         // row within half (warp-uniform)
        sum += uk * (xv.x * vv.x + xv.y * vv.y + xv.z * vv.z + xv.w * vv.w);
    }

    // block reduce 256 -> 1
    #pragma unroll
    for (int o = 16; o; o >>= 1) sum += __shfl_down_sync(0xffffffffu, sum, o);
    if ((t & 31) == 0) sred[t >> 5] = sum;
    __syncthreads();
    if (t == 0) {
        float s = 0.0f;
        #pragma unroll
        for (int w = 0; w < 8; ++w) s += sred[w];
        g_partial[b * HALVES + q] = s;
        __threadfence();                                   // partial visible before count
        unsigned int old = atomicAdd(&g_done, 1u);
        s_last = (old == TOTAL_CTAS - 1u);
    }
    __syncthreads();

    if (s_last) {
        __threadfence();                                   // see all partials
        // 256 threads: thread t finalizes batch t (fixed order -> deterministic)
        float s = g_partial[t * HALVES + 0] + g_partial[t * HALVES + 1] + bias[0];
        out[t] = 1.0f / (1.0f + expf(-s));
        __syncthreads();
        if (t == 0) g_done = 0;                            // reset for next replay
    }
}

extern "C" void kernel_launch(void* const* d_in, const int* in_sizes, int n_in,
                              void* d_out, int out_size) {
    const float* x    = (const float*)d_in[0];
    const float* wh   = (const float*)d_in[1];
    const float* wv   = (const float*)d_in[2];
    const float* bias = (const float*)d_in[3];
    float* out = (float*)d_out;

    dct_prep<<<32, 512>>>(wh, wv);
    dim3 grid(HALVES, BATCH);
    dct_main<<<grid, 256>>>(x, bias, out);
}

// round 13
// speedup vs baseline: 1.1003x; 1.1003x over previous
#include <cuda_runtime.h>
#include <cuda_bf16.h>
#include <math.h>

// result[b] = sigmoid( u^T X_b v + bias ),  u = basis^T w_h, v = basis^T w_v
// N = 512, BATCH = 256. x is (256, 512*512) fp32. Output (256,1) fp32.
//
// Single fused kernel: 512 CTAs. Each CTA (q,b) first computes ONE u value and
// ONE v value (gid = b*2+q), publishes them, spins until all 512 are ready,
// then streams its half-batch of x. Last CTA finalizes. This removes the
// separate prep kernel and its launch boundary, and spreads the ~262k cosf
// evaluations across every SM.

#define NN 512
#define BATCH 256
#define HALVES 2                       // half-batches per batch
#define HALF_F4 32768                  // float4s per half-batch (512 KB)
#define TOTAL_CTAS (BATCH * HALVES)    // 512 — single co-resident wave

__device__ __align__(16) float g_u[NN];
__device__ __align__(16) float g_v[NN];
__device__ float g_partial[BATCH * HALVES];
__device__ unsigned int g_ready = 0;   // u/v publication counter
__device__ unsigned int g_done  = 0;   // main completion counter

// __launch_bounds__(256, 4): min 4 CTAs/SM caps regs at 64 -> all 512 CTAs
// are guaranteed co-resident (528+ slots), making the grid-wide spin safe.
__global__ __launch_bounds__(256, 4) void dct_all(const float* __restrict__ x,
                                                  const float* __restrict__ wh,
                                                  const float* __restrict__ wv,
                                                  const float* __restrict__ bias,
                                                  float* __restrict__ out) {
    __shared__ float4 sv4[NN / 4];   // all 512 v values
    __shared__ float su[256];        // u values for this half-batch
    __shared__ float sred[8];
    __shared__ float spa[8], spb[8]; // phase-A cross-warp partials
    __shared__ bool s_last;

    const int t = threadIdx.x;
    const int q = blockIdx.x;        // half index (0 or 1)
    const int b = blockIdx.y;
    const int gid = b * HALVES + q;  // 0..511 — this CTA owns u[gid], v[gid]

    // ---------------- Phase A: compute u[gid], v[gid] ----------------
    // u[k] = sum_i wh[i] * cu[i] * cos((2k+1) i pi / (2N)); same cos for v.
    // Integer phase mod 4N keeps the cosf argument in [0, 2pi) — full
    // accuracy (sigmoid saturation amplifies absolute error, so fast-math
    // __cosf is deliberately NOT used).
    {
        const int i0 = t;
        const int i1 = t + 256;
        const float cu0 = (i0 == 0) ? 0.04419417382415922f : 0.0625f;
        const int twokp1 = 2 * gid + 1;
        const int m0 = (twokp1 * i0) & 2047;                 // mod 4N
        const int m1 = (twokp1 * i1) & 2047;
        const float c0 = cu0     * cosf((float)m0 * 0.0030679615757712823f);
        const float c1 = 0.0625f * cosf((float)m1 * 0.0030679615757712823f);

        float tu = wh[i0] * c0 + wh[i1] * c1;
        float tv = wv[i0] * c0 + wv[i1] * c1;

        #pragma unroll
        for (int o = 16; o; o >>= 1) {
            tu += __shfl_down_sync(0xffffffffu, tu, o);
            tv += __shfl_down_sync(0xffffffffu, tv, o);
        }
        const int w = t >> 5, lane = t & 31;
        if (lane == 0) { spa[w] = tu; spb[w] = tv; }
        __syncthreads();
        if (w == 0 && lane < 8) {
            tu = spa[lane];
            tv = spb[lane];
            #pragma unroll
            for (int o = 4; o; o >>= 1) {
                tu += __shfl_down_sync(0x000000ffu, tu, o);
                tv += __shfl_down_sync(0x000000ffu, tv, o);
            }
            if (lane == 0) {
                g_u[gid] = tu;
                g_v[gid] = tv;
                __threadfence();                 // publish before counting
                atomicAdd(&g_ready, 1u);
            }
        }
    }

    // ---------------- Phase B: wait for all 512 u/v values ----------------
    if (t == 0) {
        while (atomicAdd(&g_ready, 0u) < (unsigned)TOTAL_CTAS) __nanosleep(64);
        __threadfence();                         // order subsequent g_u/g_v reads
    }
    __syncthreads();

    // Stage v (float4, conflict-free LDS.128) and this half's u into shared.
    if (t < 128) sv4[t] = reinterpret_cast<const float4*>(g_v)[t];
    su[t] = g_u[q * 256 + t];
    __syncthreads();

    // ---------------- Main: stream 512 KB of x ----------------
    const float4* xp = reinterpret_cast<const float4*>(x)
                     + ((size_t)b << 16) + ((size_t)q << 15);

    float sum = 0.0f;
    #pragma unroll 16
    for (int i = t; i < HALF_F4; i += 256) {
        const float4 xv = __ldcs(xp + i);    // streaming: no reuse, evict-first
        const float4 vv = sv4[i & 127];      // l-group = i mod 128
        const float uk = su[i >> 7];         // row within half (warp-uniform)
        sum += uk * (xv.x * vv.x + xv.y * vv.y + xv.z * vv.z + xv.w * vv.w);
    }

    // block reduce 256 -> 1
    #pragma unroll
    for (int o = 16; o; o >>= 1) sum += __shfl_down_sync(0xffffffffu, sum, o);
    if ((t & 31) == 0) sred[t >> 5] = sum;
    __syncthreads();
    if (t == 0) {
        float s = 0.0f;
        #pragma unroll
        for (int w = 0; w < 8; ++w) s += sred[w];
        g_partial[b * HALVES + q] = s;
        __threadfence();                                   // partial visible before count
        unsigned int old = atomicAdd(&g_done, 1u);
        s_last = (old == TOTAL_CTAS - 1u);
    }
    __syncthreads();

    // ---------------- Last CTA finalizes + resets counters ----------------
    if (s_last) {
        __threadfence();                                   // see all partials
        float s = g_partial[t * HALVES + 0] + g_partial[t * HALVES + 1] + bias[0];
        out[t] = 1.0f / (1.0f + expf(-s));                 // fixed order -> deterministic
        __syncthreads();
        if (t == 0) { g_done = 0; g_ready = 0; }           // reset for next replay
    }
}

extern "C" void kernel_launch(void* const* d_in, const int* in_sizes, int n_in,
                              void* d_out, int out_size) {
    const float* x    = (const float*)d_in[0];
    const float* wh   = (const float*)d_in[1];
    const float* wv   = (const float*)d_in[2];
    const float* bias = (const float*)d_in[3];
    float* out = (float*)d_out;

    dim3 grid(HALVES, BATCH);
    dct_all<<<grid, 256>>>(x, wh, wv, bias, out);
}